// round 4
// baseline (speedup 1.0000x reference)
#include <cuda_runtime.h>
#include <cstdint>

// 2x2 Haar DWT, fp32.
// Input:  x  (16, 1, 2048, 2048)  -> 64M floats
// Output: [ll | lh | hl | hh], each (16, 1, 1024, 1024), concatenated -> 64M floats
//
// ll = 0.5*( a + b + c + d)
// lh = 0.5*(-a + b - c + d)
// hl = 0.5*(-a - b + c + d)
// hh = 0.5*( a - b - c + d)
// _safe(): non-finite -> 0 on inputs and outputs.
//
// R4: 8 output cols/thread (MLP=8 front-batched LDG.128) + streaming cache
// hints (.cs) on all global loads/stores — pure DRAM-stream kernel, nothing
// is ever re-read, so keep it out of L2's retention path.

static constexpr int B   = 16;
static constexpr int H   = 2048;
static constexpr int W   = 2048;
static constexpr int OH  = H / 2;   // 1024
static constexpr int OW  = W / 2;   // 1024
static constexpr long long SUB_ELEMS = (long long)B * OH * OW;  // 16M per subband

__device__ __forceinline__ float safef(float v) {
    return ((__float_as_uint(v) & 0x7f800000u) == 0x7f800000u) ? 0.0f : v;
}

__device__ __forceinline__ float4 safe4(float4 v) {
    v.x = safef(v.x); v.y = safef(v.y); v.z = safef(v.z); v.w = safef(v.w);
    return v;
}

__global__ __launch_bounds__(256)
void dwt2d_haar_kernel(const float* __restrict__ x, float* __restrict__ out) {
    // Each thread: 8 output columns of one output row.
    // Total threads = B * OH * (OW/8) = 16 * 1024 * 128 = 2,097,152
    const int t = blockIdx.x * blockDim.x + threadIdx.x;
    const int g  = t & 127;        // col group (OW/8 = 128 groups)
    const int rn = t >> 7;
    const int r  = rn & (OH - 1);
    const int n  = rn >> 10;
    if (n >= B) return;

    const long long in_base = (long long)n * H * W + (long long)(2 * r) * W + 16 * g;
    const float4* row0 = (const float4*)(x + in_base);
    const float4* row1 = (const float4*)(x + in_base + W);

    // Front-batch all 8 loads (MLP=8), streaming hint
    float4 p[4], q[4];
#pragma unroll
    for (int i = 0; i < 4; i++) p[i] = __ldcs(row0 + i);
#pragma unroll
    for (int i = 0; i < 4; i++) q[i] = __ldcs(row1 + i);
#pragma unroll
    for (int i = 0; i < 4; i++) { p[i] = safe4(p[i]); q[i] = safe4(q[i]); }

    float4 ll[2], lh[2], hl[2], hh[2];
    float* llp = &ll[0].x; float* lhp = &lh[0].x;
    float* hlp = &hl[0].x; float* hhp = &hh[0].x;

#pragma unroll
    for (int i = 0; i < 4; i++) {
        // pair 2i:   (p[i].x, p[i].y) over (q[i].x, q[i].y)
        // pair 2i+1: (p[i].z, p[i].w) over (q[i].z, q[i].w)
        {
            float s_ab = p[i].x + p[i].y;
            float d_ab = p[i].y - p[i].x;
            float s_cd = q[i].x + q[i].y;
            float d_cd = q[i].y - q[i].x;
            llp[2*i]   = safef(0.5f * (s_ab + s_cd));
            lhp[2*i]   = safef(0.5f * (d_ab + d_cd));
            hlp[2*i]   = safef(0.5f * (s_cd - s_ab));
            hhp[2*i]   = safef(0.5f * (d_cd - d_ab));
        }
        {
            float s_ab = p[i].z + p[i].w;
            float d_ab = p[i].w - p[i].z;
            float s_cd = q[i].z + q[i].w;
            float d_cd = q[i].w - q[i].z;
            llp[2*i+1] = safef(0.5f * (s_ab + s_cd));
            lhp[2*i+1] = safef(0.5f * (d_ab + d_cd));
            hlp[2*i+1] = safef(0.5f * (s_cd - s_ab));
            hhp[2*i+1] = safef(0.5f * (d_cd - d_ab));
        }
    }

    const long long out_base = (long long)n * OH * OW + (long long)r * OW + 8 * g;
    float4* o_ll = (float4*)(out + out_base);
    float4* o_lh = (float4*)(out + out_base + SUB_ELEMS);
    float4* o_hl = (float4*)(out + out_base + 2 * SUB_ELEMS);
    float4* o_hh = (float4*)(out + out_base + 3 * SUB_ELEMS);
    __stcs(o_ll + 0, ll[0]);  __stcs(o_ll + 1, ll[1]);
    __stcs(o_lh + 0, lh[0]);  __stcs(o_lh + 1, lh[1]);
    __stcs(o_hl + 0, hl[0]);  __stcs(o_hl + 1, hl[1]);
    __stcs(o_hh + 0, hh[0]);  __stcs(o_hh + 1, hh[1]);
}

extern "C" void kernel_launch(void* const* d_in, const int* in_sizes, int n_in,
                              void* d_out, int out_size) {
    const float* x = (const float*)d_in[0];
    float* out = (float*)d_out;
    const long long total_threads = (long long)B * OH * (OW / 8);  // 2,097,152
    const int block = 256;
    const int grid = (int)((total_threads + block - 1) / block);   // 8192
    dwt2d_haar_kernel<<<grid, block>>>(x, out);
}

// round 8
// speedup vs baseline: 1.1157x; 1.1157x over previous
#include <cuda_runtime.h>
#include <cstdint>

// 2x2 Haar DWT, fp32.
// Input:  x  (16, 1, 2048, 2048)  -> 64M floats
// Output: [ll | lh | hl | hh], each (16, 1, 1024, 1024), concatenated -> 64M floats
//
// ll = 0.5*( a + b + c + d)
// lh = 0.5*(-a + b - c + d)
// hl = 0.5*(-a - b + c + d)
// hh = 0.5*( a - b - c + d)
// _safe(): non-finite -> 0 on inputs and outputs.
//
// R5: exact R3 layout (4 output cols/thread — best measured: 75us, DRAM 81.6%)
// + ONE change: streaming stores (__stcs). Outputs are write-once; evict-first
// marking keeps dirty lines from lingering in L2's retention path.

static constexpr int B   = 16;
static constexpr int H   = 2048;
static constexpr int W   = 2048;
static constexpr int OH  = H / 2;   // 1024
static constexpr int OW  = W / 2;   // 1024
static constexpr long long SUB_ELEMS = (long long)B * OH * OW;  // 16M per subband

__device__ __forceinline__ float safef(float v) {
    // finite check via exponent bits (robust under fast-math)
    return ((__float_as_uint(v) & 0x7f800000u) == 0x7f800000u) ? 0.0f : v;
}

__device__ __forceinline__ float4 safe4(float4 v) {
    v.x = safef(v.x); v.y = safef(v.y); v.z = safef(v.z); v.w = safef(v.w);
    return v;
}

__global__ __launch_bounds__(256)
void dwt2d_haar_kernel(const float* __restrict__ x, float* __restrict__ out) {
    // Each thread: 4 output columns of one output row.
    // Total threads = B * OH * (OW/4) = 16 * 1024 * 256 = 4,194,304
    const int t = blockIdx.x * blockDim.x + threadIdx.x;
    const int groups_per_row = OW / 4;                    // 256
    const int g = t & (groups_per_row - 1);               // col group
    const int rn = t >> 8;                                // r + n*OH combined
    const int r = rn & (OH - 1);
    const int n = rn >> 10;
    if (n >= B) return;

    const long long in_base  = (long long)n * H * W + (long long)(2 * r) * W + 8 * g;
    const float4* row0 = (const float4*)(x + in_base);
    const float4* row1 = (const float4*)(x + in_base + W);

    float4 p0 = safe4(row0[0]);   // a0 b0 a1 b1
    float4 p1 = safe4(row0[1]);   // a2 b2 a3 b3
    float4 q0 = safe4(row1[0]);   // c0 d0 c1 d1
    float4 q1 = safe4(row1[1]);   // c2 d2 c3 d3

    float a[4] = {p0.x, p0.z, p1.x, p1.z};
    float b[4] = {p0.y, p0.w, p1.y, p1.w};
    float c[4] = {q0.x, q0.z, q1.x, q1.z};
    float d[4] = {q0.y, q0.w, q1.y, q1.w};

    float4 ll, lh, hl, hh;
    float* llp = &ll.x; float* lhp = &lh.x; float* hlp = &hl.x; float* hhp = &hh.x;
#pragma unroll
    for (int i = 0; i < 4; i++) {
        float s_ab = a[i] + b[i];
        float d_ab = b[i] - a[i];
        float s_cd = c[i] + d[i];
        float d_cd = d[i] - c[i];
        llp[i] = safef(0.5f * (s_ab + s_cd));
        lhp[i] = safef(0.5f * (d_ab + d_cd));
        hlp[i] = safef(0.5f * (s_cd - s_ab));
        hhp[i] = safef(0.5f * (d_cd - d_ab));
    }

    const long long out_base = (long long)n * OH * OW + (long long)r * OW + 4 * g;
    float4* o_ll = (float4*)(out + out_base);
    float4* o_lh = (float4*)(out + out_base + SUB_ELEMS);
    float4* o_hl = (float4*)(out + out_base + 2 * SUB_ELEMS);
    float4* o_hh = (float4*)(out + out_base + 3 * SUB_ELEMS);
    __stcs(o_ll, ll);
    __stcs(o_lh, lh);
    __stcs(o_hl, hl);
    __stcs(o_hh, hh);
}

extern "C" void kernel_launch(void* const* d_in, const int* in_sizes, int n_in,
                              void* d_out, int out_size) {
    const float* x = (const float*)d_in[0];
    float* out = (float*)d_out;
    const long long total_threads = (long long)B * OH * (OW / 4);  // 4,194,304
    const int block = 256;
    const int grid = (int)((total_threads + block - 1) / block);   // 16384
    dwt2d_haar_kernel<<<grid, block>>>(x, out);
}